// round 14
// baseline (speedup 1.0000x reference)
#include <cuda_runtime.h>
#include <cuda_fp16.h>
#include <cstdint>

// ShallowLSTM via mma.sync m16n8k16 fp16->fp32, generic PTX.
// B=8192, T=180, I=7, H=64, O=16. 128 CTAs x 64 batch, 512 threads (16 warps).
// R14 = R13 (B passes 0-1 register-resident, 15 LDSM4/warp/step, pipelined
// MMA/epilogue) + R12 paired f16x2 epilogue (tanh.approx.f16x2, 5 MUFU per
// 2 cells; sigmoid x0.5 folded into B's i/f/o rows). MUFU/SMSP/step 2560->1280.
// K=80: [h_hi(64) | x_hi(7) x_hi(7) b_hi b_lo]. c kept in f32.

#define T_STEPS 180
#define IDIM    7
#define HID     64
#define TB      64
#define NTHR    512
#define ODIM    16

#define SA      176           // A row stride bytes (80 halves + pad)
#define SB      176           // B row stride bytes (80 halves + pad)
#define ABUF    11264         // 64*SA
#define OFF_B   22528
#define OFF_HF  67584         // 64*68 floats = 17408
#define OFF_WFC 84992
#define OFF_BFC 89088
#define SMEM_TOTAL 89152

__device__ __forceinline__ uint32_t smem_u32(const void* p) {
    uint32_t a;
    asm("{ .reg .u64 t; cvta.to.shared.u64 t, %1; cvt.u32.u64 %0, t; }" : "=r"(a) : "l"(p));
    return a;
}
union H2U { __half2 h; uint32_t u; };
__device__ __forceinline__ __half2 tanh2(__half2 v) {
    H2U a, r; a.h = v;
    asm("tanh.approx.f16x2 %0, %1;" : "=r"(r.u) : "r"(a.u));
    return r.h;
}

#define LDSM4(r, addr) \
    asm volatile("ldmatrix.sync.aligned.m8n8.x4.shared.b16 {%0,%1,%2,%3}, [%4];" \
        : "=r"((r)[0]), "=r"((r)[1]), "=r"((r)[2]), "=r"((r)[3]) : "r"(addr))

#define MMA(d, a, b0, b1) \
    asm volatile("mma.sync.aligned.m16n8k16.row.col.f32.f16.f16.f32 " \
        "{%0,%1,%2,%3},{%4,%5,%6,%7},{%8,%9},{%0,%1,%2,%3};" \
        : "+f"((d)[0]), "+f"((d)[1]), "+f"((d)[2]), "+f"((d)[3]) \
        : "r"((a)[0]), "r"((a)[1]), "r"((a)[2]), "r"((a)[3]), "r"(b0), "r"(b1))

// Pass from register-resident B (passes 0,1)
#define MMA_PASS_REG(p) do { \
    _Pragma("unroll") \
    for (int cb = 0; cb < 4; ++cb) { \
        MMA(acc[2*(p)],   ah[cb], breg[p][cb][0], breg[p][cb][1]); \
        MMA(acc[2*(p)+1], ah[cb], breg[p][cb][2], breg[p][cb][3]); \
    } \
    MMA(acc[2*(p)],   ax, breg[p][4][0], breg[p][4][1]); \
    MMA(acc[2*(p)+1], ax, breg[p][4][2], breg[p][4][3]); \
} while (0)

// Pass streamed from SMEM (passes 2,3)
#define MMA_PASS_LDS(p) do { \
    uint32_t bb[4]; \
    _Pragma("unroll") \
    for (int cb = 0; cb < 4; ++cb) { \
        LDSM4(bb, b_l + (uint32_t)((p) * 16 * SB + cb * 32)); \
        MMA(acc[2*(p)],   ah[cb], bb[0], bb[1]); \
        MMA(acc[2*(p)+1], ah[cb], bb[2], bb[3]); \
    } \
    LDSM4(bb, b_l + (uint32_t)((p) * 16 * SB + 4 * 32)); \
    MMA(acc[2*(p)],   ax, bb[0], bb[1]); \
    MMA(acc[2*(p)+1], ax, bb[2], bb[3]); \
} while (0)

__global__ void __launch_bounds__(NTHR, 1) lstm_mma(
    const float* __restrict__ x,
    const float* __restrict__ W_ih,
    const float* __restrict__ W_hh,
    const float* __restrict__ b_ih,
    const float* __restrict__ b_hh,
    const float* __restrict__ W_fc,
    const float* __restrict__ b_fc,
    float* __restrict__ out)
{
    extern __shared__ char sm[];
    float* hf  = (float*)(sm + OFF_HF);
    float* wfc = (float*)(sm + OFF_WFC);
    float* bfc = (float*)(sm + OFF_BFC);

    const int tid  = threadIdx.x;
    const int w    = tid >> 5;
    const int lane = tid & 31;
    const int grp  = w >> 2;            // 4 groups of 4 warps, 16 batch rows each
    const int wn   = w & 3;
    const int mrow = grp * 16;
    const int ncol = wn * 64;
    const int bbase = blockIdx.x * TB;

    // ---- build B [256 n][80 k] fp16 (n = 4*j + gate reorder) ----
    // i/f/o gate rows (and bias) pre-scaled by 0.5: sigmoid(x)=0.5+0.5*tanh(x/2)
    for (int idx = tid; idx < 256 * 80; idx += NTHR) {
        int n = idx / 80, k = idx - n * 80;
        int r = (n & 3) * 64 + (n >> 2);
        float gsc = ((n & 3) == 2) ? 1.0f : 0.5f;   // g gate unscaled
        float v = 0.f; int lo = 0;
        if      (k < 64)  v = W_hh[r * 64 + k];
        else if (k < 71)  v = W_ih[r * 7 + (k - 64)];
        else if (k < 78)  { v = W_ih[r * 7 + (k - 71)]; lo = 1; }
        else if (k == 78) v = b_ih[r] + b_hh[r];
        else              { v = b_ih[r] + b_hh[r]; lo = 1; }
        v *= gsc;
        __half hv = __float2half_rn(v);
        if (lo) hv = __float2half_rn(v - __half2float(hv));
        *(__half*)(sm + OFF_B + n * SB + k * 2) = hv;
    }
    // zero both A buffers
    for (int idx = tid; idx < (2 * ABUF) / 4; idx += NTHR)
        ((uint32_t*)sm)[idx] = 0u;
    for (int idx = tid; idx < ODIM * HID; idx += NTHR) wfc[idx] = W_fc[idx];
    if (tid < ODIM) bfc[tid] = b_fc[tid];
    __syncthreads();

    // ones in bias slots (both buffers), x(0) into buf0
    if (tid < TB) {
        __half one = __float2half_rn(1.0f);
        #pragma unroll
        for (int bs = 0; bs < 2; ++bs) {
            char* ab = sm + bs * ABUF + tid * SA;
            *(__half*)(ab + 78 * 2) = one;
            *(__half*)(ab + 79 * 2) = one;
        }
    }
    const bool is_xw = (wn == 0) && (lane < 16);
    const int xrow   = mrow + (lane & 15);
    const float* xp  = x + (size_t)(bbase + xrow) * (T_STEPS * IDIM);
    if (is_xw) {
        char* ab = sm + xrow * SA;
        #pragma unroll
        for (int i = 0; i < IDIM; ++i) {
            __half hh = __float2half_rn(xp[i]);
            *(__half*)(ab + (64 + i) * 2) = hh;
            *(__half*)(ab + (71 + i) * 2) = hh;   // dup, pairs with Wx_lo
        }
    }
    __syncthreads();

    const uint32_t sm32 = smem_u32(sm);
    const uint32_t a_l = (uint32_t)((mrow + (lane & 15)) * SA + ((lane >> 4) << 4));
    const uint32_t b_l = sm32 + OFF_B +
        (uint32_t)((ncol + (lane & 7) + ((lane >> 4) << 3)) * SB + (((lane >> 3) & 1) << 4));

    // ---- hoist B passes 0,1 into registers (static across all steps) ----
    uint32_t breg[2][5][4];
    #pragma unroll
    for (int p = 0; p < 2; ++p)
        #pragma unroll
        for (int cb = 0; cb < 5; ++cb)
            LDSM4(breg[p][cb], b_l + (uint32_t)(p * 16 * SB + cb * 32));

    float cst[8];
    #pragma unroll
    for (int i = 0; i < 8; ++i) cst[i] = 0.f;

    const int lodd = lane & 1;
    const int erow = (lane >> 2) + ((lane & 1) << 3);   // within group
    const int ejc  = (lane >> 1) & 1;
    const __half2 HALF2 = __float2half2_rn(0.5f);

    for (int t = 0; t < T_STEPS; ++t) {
        const uint32_t aB = sm32 + (uint32_t)((t & 1) * ABUF);
        char* anext = sm + ((t + 1) & 1) * ABUF;

        float acc[8][4];
        #pragma unroll
        for (int nt = 0; nt < 8; ++nt)
            #pragma unroll
            for (int q = 0; q < 4; ++q) acc[nt][q] = 0.f;

        // hoist A chunks: h_hi 0-3, x/bias chunk 4
        uint32_t ah[4][4], ax[4];
        #pragma unroll
        for (int c = 0; c < 4; ++c) LDSM4(ah[c], aB + a_l + (uint32_t)(c * 32));
        LDSM4(ax, aB + a_l + (uint32_t)(4 * 32));

        // prefetch x(t+1) during GEMM
        float xr[IDIM];
        const bool dox = is_xw && (t + 1 < T_STEPS);
        if (dox) {
            #pragma unroll
            for (int i = 0; i < IDIM; ++i) xr[i] = __ldg(xp + (t + 1) * IDIM + i);
        }

        // ---- pipelined: MMA(p+1) issues before epilogue(p) ----
        MMA_PASS_REG(0);
        #pragma unroll
        for (int p = 0; p < 4; ++p) {
            if (p == 0) MMA_PASS_REG(1);
            else if (p == 1) MMA_PASS_LDS(2);
            else if (p == 2) MMA_PASS_LDS(3);

            // paired epilogue for cells nt0=2p, nt1=2p+1 (f16x2 tanh forms)
            float iv[2], fv[2], gv[2], ov[2];
            #pragma unroll
            for (int s = 0; s < 2; ++s) {
                const int nt = 2 * p + s;
                float a0 = acc[nt][0], a1 = acc[nt][1];
                float a2 = acc[nt][2], a3 = acc[nt][3];
                float s0 = lodd ? a0 : a2;
                float s1 = lodd ? a1 : a3;
                float o0 = __shfl_xor_sync(0xffffffffu, s0, 1);
                float o1 = __shfl_xor_sync(0xffffffffu, s1, 1);
                iv[s] = lodd ? o0 : a0;
                fv[s] = lodd ? o1 : a1;
                gv[s] = lodd ? a2 : o0;
                ov[s] = lodd ? a3 : o1;
            }
            __half2 ti = tanh2(__floats2half2_rn(iv[0], iv[1]));
            __half2 tf = tanh2(__floats2half2_rn(fv[0], fv[1]));
            __half2 to = tanh2(__floats2half2_rn(ov[0], ov[1]));
            __half2 tg = tanh2(__floats2half2_rn(gv[0], gv[1]));
            __half2 ig = __hfma2(ti, HALF2, HALF2);
            __half2 fg = __hfma2(tf, HALF2, HALF2);
            __half2 og = __hfma2(to, HALF2, HALF2);
            __half2 pr = __hmul2(ig, tg);
            float cn0 = fmaf(__low2float(fg),  cst[2 * p],     __low2float(pr));
            float cn1 = fmaf(__high2float(fg), cst[2 * p + 1], __high2float(pr));
            cst[2 * p]     = cn0;
            cst[2 * p + 1] = cn1;
            __half2 h2 = __hmul2(og, tanh2(__floats2half2_rn(cn0, cn1)));

            int row = mrow + erow;
            int j0  = (ncol >> 2) + (2 * p) * 2 + ejc;
            *(__half*)(anext + row * SA + j0 * 2)       = __low2half(h2);
            *(__half*)(anext + row * SA + (j0 + 2) * 2) = __high2half(h2);
            if (t == T_STEPS - 1) {
                hf[row * 68 + j0]     = __low2float(h2);
                hf[row * 68 + j0 + 2] = __high2float(h2);
            }
        }

        // store x(t+1)
        if (dox) {
            char* ab = anext + xrow * SA;
            #pragma unroll
            for (int i = 0; i < IDIM; ++i) {
                __half hh = __float2half_rn(xr[i]);
                *(__half*)(ab + (64 + i) * 2) = hh;
                *(__half*)(ab + (71 + i) * 2) = hh;
            }
        }

        asm volatile("bar.sync %0, %1;" :: "r"(grp + 1), "r"(128) : "memory");
    }

    __syncthreads();

    // ---- final FC ----
    if (tid < 128) {
        int b  = tid >> 1;
        int ob = (tid & 1) * 8;
        float acc_o[8];
        #pragma unroll
        for (int oo = 0; oo < 8; ++oo) acc_o[oo] = bfc[ob + oo];
        for (int kk = 0; kk < HID; kk += 4) {
            float4 hv = *(float4*)&hf[b * 68 + kk];
            #pragma unroll
            for (int oo = 0; oo < 8; ++oo) {
                float4 wf = *(float4*)&wfc[(ob + oo) * HID + kk];
                acc_o[oo] += hv.x * wf.x + hv.y * wf.y + hv.z * wf.z + hv.w * wf.w;
            }
        }
        #pragma unroll
        for (int oo = 0; oo < 8; ++oo)
            out[(size_t)(bbase + b) * ODIM + ob + oo] = acc_o[oo];
    }
}

extern "C" void kernel_launch(void* const* d_in, const int* in_sizes, int n_in,
                              void* d_out, int out_size) {
    const float* x    = (const float*)d_in[0];
    const float* W_ih = (const float*)d_in[1];
    const float* W_hh = (const float*)d_in[2];
    const float* b_ih = (const float*)d_in[3];
    const float* b_hh = (const float*)d_in[4];
    const float* W_fc = (const float*)d_in[5];
    const float* b_fc = (const float*)d_in[6];
    float* out = (float*)d_out;

    int B = in_sizes[0] / (T_STEPS * IDIM);   // 8192
    int nblocks = B / TB;                     // 128

    cudaFuncSetAttribute(lstm_mma, cudaFuncAttributeMaxDynamicSharedMemorySize, SMEM_TOTAL);
    lstm_mma<<<nblocks, NTHR, SMEM_TOTAL>>>(x, W_ih, W_hh, b_ih, b_hh, W_fc, b_fc, out);
}

// round 15
// speedup vs baseline: 1.2156x; 1.2156x over previous
#include <cuda_runtime.h>
#include <cuda_fp16.h>
#include <cstdint>

// ShallowLSTM via mma.sync m16n8k16 fp16->fp32, generic PTX.
// B=8192, T=180, I=7, H=64, O=16. 128 CTAs x 64 batch, 512 threads (16 warps).
// R15 = R13 (B passes 0-1 register-resident, pipelined MMA/epilogue, f32
// tanh.approx) + SHFL-FREE epilogue: gate columns permuted so each thread's
// mma fragments hold all 4 gates of its cells directly (i,f in even n8-tile,
// g,o in odd tile, columns 2q,2q+1). Sigmoid x0.5 folded into i/f/o weight
// rows (exact power-of-2 scale -> bit-identical numerics).
// K=80: [h_hi(64) | x_hi(7) x_hi(7) b_hi b_lo].

#define T_STEPS 180
#define IDIM    7
#define HID     64
#define TB      64
#define NTHR    512
#define ODIM    16

#define SA      176           // A row stride bytes (80 halves + pad)
#define SB      176           // B row stride bytes (80 halves + pad)
#define ABUF    11264         // 64*SA
#define OFF_B   22528
#define OFF_HF  67584         // 64*68 floats = 17408
#define OFF_WFC 84992
#define OFF_BFC 89088
#define SMEM_TOTAL 89152

__device__ __forceinline__ uint32_t smem_u32(const void* p) {
    uint32_t a;
    asm("{ .reg .u64 t; cvta.to.shared.u64 t, %1; cvt.u32.u64 %0, t; }" : "=r"(a) : "l"(p));
    return a;
}
__device__ __forceinline__ float tanh_ap(float v) {
    float r;
    asm("tanh.approx.f32 %0, %1;" : "=f"(r) : "f"(v));
    return r;
}

#define LDSM4(r, addr) \
    asm volatile("ldmatrix.sync.aligned.m8n8.x4.shared.b16 {%0,%1,%2,%3}, [%4];" \
        : "=r"((r)[0]), "=r"((r)[1]), "=r"((r)[2]), "=r"((r)[3]) : "r"(addr))

#define MMA(d, a, b0, b1) \
    asm volatile("mma.sync.aligned.m16n8k16.row.col.f32.f16.f16.f32 " \
        "{%0,%1,%2,%3},{%4,%5,%6,%7},{%8,%9},{%0,%1,%2,%3};" \
        : "+f"((d)[0]), "+f"((d)[1]), "+f"((d)[2]), "+f"((d)[3]) \
        : "r"((a)[0]), "r"((a)[1]), "r"((a)[2]), "r"((a)[3]), "r"(b0), "r"(b1))

// Pass from register-resident B (passes 0,1)
#define MMA_PASS_REG(p) do { \
    _Pragma("unroll") \
    for (int cb = 0; cb < 4; ++cb) { \
        MMA(acc[2*(p)],   ah[cb], breg[p][cb][0], breg[p][cb][1]); \
        MMA(acc[2*(p)+1], ah[cb], breg[p][cb][2], breg[p][cb][3]); \
    } \
    MMA(acc[2*(p)],   ax, breg[p][4][0], breg[p][4][1]); \
    MMA(acc[2*(p)+1], ax, breg[p][4][2], breg[p][4][3]); \
} while (0)

// Pass streamed from SMEM (passes 2,3)
#define MMA_PASS_LDS(p) do { \
    uint32_t bb[4]; \
    _Pragma("unroll") \
    for (int cb = 0; cb < 4; ++cb) { \
        LDSM4(bb, b_l + (uint32_t)((p) * 16 * SB + cb * 32)); \
        MMA(acc[2*(p)],   ah[cb], bb[0], bb[1]); \
        MMA(acc[2*(p)+1], ah[cb], bb[2], bb[3]); \
    } \
    LDSM4(bb, b_l + (uint32_t)((p) * 16 * SB + 4 * 32)); \
    MMA(acc[2*(p)],   ax, bb[0], bb[1]); \
    MMA(acc[2*(p)+1], ax, bb[2], bb[3]); \
} while (0)

__global__ void __launch_bounds__(NTHR, 1) lstm_mma(
    const float* __restrict__ x,
    const float* __restrict__ W_ih,
    const float* __restrict__ W_hh,
    const float* __restrict__ b_ih,
    const float* __restrict__ b_hh,
    const float* __restrict__ W_fc,
    const float* __restrict__ b_fc,
    float* __restrict__ out)
{
    extern __shared__ char sm[];
    float* hf  = (float*)(sm + OFF_HF);
    float* wfc = (float*)(sm + OFF_WFC);
    float* bfc = (float*)(sm + OFF_BFC);

    const int tid  = threadIdx.x;
    const int w    = tid >> 5;
    const int lane = tid & 31;
    const int grp  = w >> 2;            // 4 groups of 4 warps, 16 batch rows each
    const int wn   = w & 3;
    const int mrow = grp * 16;
    const int ncol = wn * 64;
    const int bbase = blockIdx.x * TB;

    // ---- build B [256 n][80 k] fp16, shfl-free gate permutation ----
    // n -> cell j = (n>>4)*4 + ((n>>1)&3), gate = ((n>>3)&1)*2 + (n&1)
    // (i,f in even n8-tile cols 2q,2q+1; g,o in odd tile). i/f/o rows and bias
    // pre-scaled by 0.5 (exact): sigmoid(x) = 0.5 + 0.5*tanh(x/2).
    for (int idx = tid; idx < 256 * 80; idx += NTHR) {
        int n = idx / 80, k = idx - n * 80;
        int j    = (n >> 4) * 4 + ((n >> 1) & 3);
        int gate = ((n >> 3) & 1) * 2 + (n & 1);
        int r = gate * 64 + j;
        float gsc = (gate == 2) ? 1.0f : 0.5f;   // g gate unscaled
        float v = 0.f; int lo = 0;
        if      (k < 64)  v = W_hh[r * 64 + k];
        else if (k < 71)  v = W_ih[r * 7 + (k - 64)];
        else if (k < 78)  { v = W_ih[r * 7 + (k - 71)]; lo = 1; }
        else if (k == 78) v = b_ih[r] + b_hh[r];
        else              { v = b_ih[r] + b_hh[r]; lo = 1; }
        v *= gsc;
        __half hv = __float2half_rn(v);
        if (lo) hv = __float2half_rn(v - __half2float(hv));
        *(__half*)(sm + OFF_B + n * SB + k * 2) = hv;
    }
    // zero both A buffers
    for (int idx = tid; idx < (2 * ABUF) / 4; idx += NTHR)
        ((uint32_t*)sm)[idx] = 0u;
    for (int idx = tid; idx < ODIM * HID; idx += NTHR) wfc[idx] = W_fc[idx];
    if (tid < ODIM) bfc[tid] = b_fc[tid];
    __syncthreads();

    // ones in bias slots (both buffers), x(0) into buf0
    if (tid < TB) {
        __half one = __float2half_rn(1.0f);
        #pragma unroll
        for (int bs = 0; bs < 2; ++bs) {
            char* ab = sm + bs * ABUF + tid * SA;
            *(__half*)(ab + 78 * 2) = one;
            *(__half*)(ab + 79 * 2) = one;
        }
    }
    const bool is_xw = (wn == 0) && (lane < 16);
    const int xrow   = mrow + (lane & 15);
    const float* xp  = x + (size_t)(bbase + xrow) * (T_STEPS * IDIM);
    if (is_xw) {
        char* ab = sm + xrow * SA;
        #pragma unroll
        for (int i = 0; i < IDIM; ++i) {
            __half hh = __float2half_rn(xp[i]);
            *(__half*)(ab + (64 + i) * 2) = hh;
            *(__half*)(ab + (71 + i) * 2) = hh;   // dup, pairs with Wx_lo
        }
    }
    __syncthreads();

    const uint32_t sm32 = smem_u32(sm);
    const uint32_t a_l = (uint32_t)((mrow + (lane & 15)) * SA + ((lane >> 4) << 4));
    const uint32_t b_l = sm32 + OFF_B +
        (uint32_t)((ncol + (lane & 7) + ((lane >> 4) << 3)) * SB + (((lane >> 3) & 1) << 4));

    // ---- hoist B passes 0,1 into registers (static across all steps) ----
    uint32_t breg[2][5][4];
    #pragma unroll
    for (int p = 0; p < 2; ++p)
        #pragma unroll
        for (int cb = 0; cb < 5; ++cb)
            LDSM4(breg[p][cb], b_l + (uint32_t)(p * 16 * SB + cb * 32));

    float cst[8];
    #pragma unroll
    for (int i = 0; i < 8; ++i) cst[i] = 0.f;

    const int erow0 = lane >> 2;        // fragment row within 16-row tile
    const int ejq   = lane & 3;         // cell q within pair

    for (int t = 0; t < T_STEPS; ++t) {
        const uint32_t aB = sm32 + (uint32_t)((t & 1) * ABUF);
        char* anext = sm + ((t + 1) & 1) * ABUF;

        float acc[8][4];
        #pragma unroll
        for (int nt = 0; nt < 8; ++nt)
            #pragma unroll
            for (int q = 0; q < 4; ++q) acc[nt][q] = 0.f;

        // hoist A chunks: h_hi 0-3, x/bias chunk 4
        uint32_t ah[4][4], ax[4];
        #pragma unroll
        for (int c = 0; c < 4; ++c) LDSM4(ah[c], aB + a_l + (uint32_t)(c * 32));
        LDSM4(ax, aB + a_l + (uint32_t)(4 * 32));

        // prefetch x(t+1) during GEMM
        float xr[IDIM];
        const bool dox = is_xw && (t + 1 < T_STEPS);
        if (dox) {
            #pragma unroll
            for (int i = 0; i < IDIM; ++i) xr[i] = __ldg(xp + (t + 1) * IDIM + i);
        }

        // ---- pipelined: MMA(p+1) issues before epilogue(p) ----
        MMA_PASS_REG(0);
        #pragma unroll
        for (int p = 0; p < 4; ++p) {
            if (p == 0) MMA_PASS_REG(1);
            else if (p == 1) MMA_PASS_LDS(2);
            else if (p == 2) MMA_PASS_LDS(3);

            // shfl-free epilogue for pair m=p: cells (q=lane&3, rh=0,1)
            #pragma unroll
            for (int rh = 0; rh < 2; ++rh) {
                const int ci = 2 * p + rh;
                float iv = acc[2 * p][2 * rh];
                float fv = acc[2 * p][2 * rh + 1];
                float gv = acc[2 * p + 1][2 * rh];
                float ov = acc[2 * p + 1][2 * rh + 1];
                float ig = fmaf(0.5f, tanh_ap(iv), 0.5f);
                float fg = fmaf(0.5f, tanh_ap(fv), 0.5f);
                float og = fmaf(0.5f, tanh_ap(ov), 0.5f);
                float gg = tanh_ap(gv);
                float cn = fmaf(fg, cst[ci], ig * gg);
                cst[ci] = cn;
                float hv = og * tanh_ap(cn);
                int row = mrow + erow0 + rh * 8;
                int j   = (ncol >> 2) + p * 4 + ejq;
                *(__half*)(anext + row * SA + j * 2) = __float2half_rn(hv);
                if (t == T_STEPS - 1) hf[row * 68 + j] = hv;
            }
        }

        // store x(t+1)
        if (dox) {
            char* ab = anext + xrow * SA;
            #pragma unroll
            for (int i = 0; i < IDIM; ++i) {
                __half hh = __float2half_rn(xr[i]);
                *(__half*)(ab + (64 + i) * 2) = hh;
                *(__half*)(ab + (71 + i) * 2) = hh;
            }
        }

        asm volatile("bar.sync %0, %1;" :: "r"(grp + 1), "r"(128) : "memory");
    }

    __syncthreads();

    // ---- final FC ----
    if (tid < 128) {
        int b  = tid >> 1;
        int ob = (tid & 1) * 8;
        float acc_o[8];
        #pragma unroll
        for (int oo = 0; oo < 8; ++oo) acc_o[oo] = bfc[ob + oo];
        for (int kk = 0; kk < HID; kk += 4) {
            float4 hv = *(float4*)&hf[b * 68 + kk];
            #pragma unroll
            for (int oo = 0; oo < 8; ++oo) {
                float4 wf = *(float4*)&wfc[(ob + oo) * HID + kk];
                acc_o[oo] += hv.x * wf.x + hv.y * wf.y + hv.z * wf.z + hv.w * wf.w;
            }
        }
        #pragma unroll
        for (int oo = 0; oo < 8; ++oo)
            out[(size_t)(bbase + b) * ODIM + ob + oo] = acc_o[oo];
    }
}

extern "C" void kernel_launch(void* const* d_in, const int* in_sizes, int n_in,
                              void* d_out, int out_size) {
    const float* x    = (const float*)d_in[0];
    const float* W_ih = (const float*)d_in[1];
    const float* W_hh = (const float*)d_in[2];
    const float* b_ih = (const float*)d_in[3];
    const float* b_hh = (const float*)d_in[4];
    const float* W_fc = (const float*)d_in[5];
    const float* b_fc = (const float*)d_in[6];
    float* out = (float*)d_out;

    int B = in_sizes[0] / (T_STEPS * IDIM);   // 8192
    int nblocks = B / TB;                     // 128

    cudaFuncSetAttribute(lstm_mma, cudaFuncAttributeMaxDynamicSharedMemorySize, SMEM_TOTAL);
    lstm_mma<<<nblocks, NTHR, SMEM_TOTAL>>>(x, W_ih, W_hh, b_ih, b_hh, W_fc, b_fc, out);
}

// round 16
// speedup vs baseline: 1.2207x; 1.0042x over previous
#include <cuda_runtime.h>
#include <cuda_fp16.h>
#include <cstdint>

// ShallowLSTM via mma.sync m16n8k16 fp16->fp32, generic PTX.
// B=8192, T=180, I=7, H=64, O=16. 128 CTAs x 64 batch, 512 threads (16 warps).
// R16 = R15 (shfl-free gate permutation, B passes 0-1 register-resident,
// pipelined MMA/epilogue) + low-overhead paired tanh.approx.f16x2 epilogue:
// (i,f) and (g,o) are ADJACENT acc regs -> 1 pack each; 5 tanh2 per 2 cells
// (MUFU/SMSP/step 1280 -> 640); h produced directly in f16 (no cvt stores).
// K=80: [h_hi(64) | x_hi(7) x_hi(7) b_hi b_lo]. c kept in f32.

#define T_STEPS 180
#define IDIM    7
#define HID     64
#define TB      64
#define NTHR    512
#define ODIM    16

#define SA      176           // A row stride bytes (80 halves + pad)
#define SB      176           // B row stride bytes (80 halves + pad)
#define ABUF    11264         // 64*SA
#define OFF_B   22528
#define OFF_HF  67584         // 64*68 floats = 17408
#define OFF_WFC 84992
#define OFF_BFC 89088
#define SMEM_TOTAL 89152

__device__ __forceinline__ uint32_t smem_u32(const void* p) {
    uint32_t a;
    asm("{ .reg .u64 t; cvta.to.shared.u64 t, %1; cvt.u32.u64 %0, t; }" : "=r"(a) : "l"(p));
    return a;
}
union H2U { __half2 h; uint32_t u; };
__device__ __forceinline__ __half2 tanh2(__half2 v) {
    H2U a, r; a.h = v;
    asm("tanh.approx.f16x2 %0, %1;" : "=r"(r.u) : "r"(a.u));
    return r.h;
}

#define LDSM4(r, addr) \
    asm volatile("ldmatrix.sync.aligned.m8n8.x4.shared.b16 {%0,%1,%2,%3}, [%4];" \
        : "=r"((r)[0]), "=r"((r)[1]), "=r"((r)[2]), "=r"((r)[3]) : "r"(addr))

#define MMA(d, a, b0, b1) \
    asm volatile("mma.sync.aligned.m16n8k16.row.col.f32.f16.f16.f32 " \
        "{%0,%1,%2,%3},{%4,%5,%6,%7},{%8,%9},{%0,%1,%2,%3};" \
        : "+f"((d)[0]), "+f"((d)[1]), "+f"((d)[2]), "+f"((d)[3]) \
        : "r"((a)[0]), "r"((a)[1]), "r"((a)[2]), "r"((a)[3]), "r"(b0), "r"(b1))

// Pass from register-resident B (passes 0,1)
#define MMA_PASS_REG(p) do { \
    _Pragma("unroll") \
    for (int cb = 0; cb < 4; ++cb) { \
        MMA(acc[2*(p)],   ah[cb], breg[p][cb][0], breg[p][cb][1]); \
        MMA(acc[2*(p)+1], ah[cb], breg[p][cb][2], breg[p][cb][3]); \
    } \
    MMA(acc[2*(p)],   ax, breg[p][4][0], breg[p][4][1]); \
    MMA(acc[2*(p)+1], ax, breg[p][4][2], breg[p][4][3]); \
} while (0)

// Pass streamed from SMEM (passes 2,3)
#define MMA_PASS_LDS(p) do { \
    uint32_t bb[4]; \
    _Pragma("unroll") \
    for (int cb = 0; cb < 4; ++cb) { \
        LDSM4(bb, b_l + (uint32_t)((p) * 16 * SB + cb * 32)); \
        MMA(acc[2*(p)],   ah[cb], bb[0], bb[1]); \
        MMA(acc[2*(p)+1], ah[cb], bb[2], bb[3]); \
    } \
    LDSM4(bb, b_l + (uint32_t)((p) * 16 * SB + 4 * 32)); \
    MMA(acc[2*(p)],   ax, bb[0], bb[1]); \
    MMA(acc[2*(p)+1], ax, bb[2], bb[3]); \
} while (0)

__global__ void __launch_bounds__(NTHR, 1) lstm_mma(
    const float* __restrict__ x,
    const float* __restrict__ W_ih,
    const float* __restrict__ W_hh,
    const float* __restrict__ b_ih,
    const float* __restrict__ b_hh,
    const float* __restrict__ W_fc,
    const float* __restrict__ b_fc,
    float* __restrict__ out)
{
    extern __shared__ char sm[];
    float* hf  = (float*)(sm + OFF_HF);
    float* wfc = (float*)(sm + OFF_WFC);
    float* bfc = (float*)(sm + OFF_BFC);

    const int tid  = threadIdx.x;
    const int w    = tid >> 5;
    const int lane = tid & 31;
    const int grp  = w >> 2;            // 4 groups of 4 warps, 16 batch rows each
    const int wn   = w & 3;
    const int mrow = grp * 16;
    const int ncol = wn * 64;
    const int bbase = blockIdx.x * TB;

    // ---- build B [256 n][80 k] fp16, shfl-free gate permutation ----
    // n -> cell j = (n>>4)*4 + ((n>>1)&3), gate = ((n>>3)&1)*2 + (n&1)
    // i/f/o rows and bias pre-scaled by 0.5 (exact): sigmoid(x)=0.5+0.5*tanh(x/2)
    for (int idx = tid; idx < 256 * 80; idx += NTHR) {
        int n = idx / 80, k = idx - n * 80;
        int j    = (n >> 4) * 4 + ((n >> 1) & 3);
        int gate = ((n >> 3) & 1) * 2 + (n & 1);
        int r = gate * 64 + j;
        float gsc = (gate == 2) ? 1.0f : 0.5f;   // g gate unscaled
        float v = 0.f; int lo = 0;
        if      (k < 64)  v = W_hh[r * 64 + k];
        else if (k < 71)  v = W_ih[r * 7 + (k - 64)];
        else if (k < 78)  { v = W_ih[r * 7 + (k - 71)]; lo = 1; }
        else if (k == 78) v = b_ih[r] + b_hh[r];
        else              { v = b_ih[r] + b_hh[r]; lo = 1; }
        v *= gsc;
        __half hv = __float2half_rn(v);
        if (lo) hv = __float2half_rn(v - __half2float(hv));
        *(__half*)(sm + OFF_B + n * SB + k * 2) = hv;
    }
    // zero both A buffers
    for (int idx = tid; idx < (2 * ABUF) / 4; idx += NTHR)
        ((uint32_t*)sm)[idx] = 0u;
    for (int idx = tid; idx < ODIM * HID; idx += NTHR) wfc[idx] = W_fc[idx];
    if (tid < ODIM) bfc[tid] = b_fc[tid];
    __syncthreads();

    // ones in bias slots (both buffers), x(0) into buf0
    if (tid < TB) {
        __half one = __float2half_rn(1.0f);
        #pragma unroll
        for (int bs = 0; bs < 2; ++bs) {
            char* ab = sm + bs * ABUF + tid * SA;
            *(__half*)(ab + 78 * 2) = one;
            *(__half*)(ab + 79 * 2) = one;
        }
    }
    const bool is_xw = (wn == 0) && (lane < 16);
    const int xrow   = mrow + (lane & 15);
    const float* xp  = x + (size_t)(bbase + xrow) * (T_STEPS * IDIM);
    if (is_xw) {
        char* ab = sm + xrow * SA;
        #pragma unroll
        for (int i = 0; i < IDIM; ++i) {
            __half hh = __float2half_rn(xp[i]);
            *(__half*)(ab + (64 + i) * 2) = hh;
            *(__half*)(ab + (71 + i) * 2) = hh;   // dup, pairs with Wx_lo
        }
    }
    __syncthreads();

    const uint32_t sm32 = smem_u32(sm);
    const uint32_t a_l = (uint32_t)((mrow + (lane & 15)) * SA + ((lane >> 4) << 4));
    const uint32_t b_l = sm32 + OFF_B +
        (uint32_t)((ncol + (lane & 7) + ((lane >> 4) << 3)) * SB + (((lane >> 3) & 1) << 4));

    // ---- hoist B passes 0,1 into registers (static across all steps) ----
    uint32_t breg[2][5][4];
    #pragma unroll
    for (int p = 0; p < 2; ++p)
        #pragma unroll
        for (int cb = 0; cb < 5; ++cb)
            LDSM4(breg[p][cb], b_l + (uint32_t)(p * 16 * SB + cb * 32));

    float cst[8];
    #pragma unroll
    for (int i = 0; i < 8; ++i) cst[i] = 0.f;

    const int erow0 = lane >> 2;        // fragment row within 16-row tile
    const int ejq   = lane & 3;         // cell q within pair
    const __half2 H55  = __floats2half2_rn(0.5f, 0.5f);
    const __half2 H105 = __floats2half2_rn(1.0f, 0.5f);
    const __half2 H005 = __floats2half2_rn(0.0f, 0.5f);

    for (int t = 0; t < T_STEPS; ++t) {
        const uint32_t aB = sm32 + (uint32_t)((t & 1) * ABUF);
        char* anext = sm + ((t + 1) & 1) * ABUF;

        float acc[8][4];
        #pragma unroll
        for (int nt = 0; nt < 8; ++nt)
            #pragma unroll
            for (int q = 0; q < 4; ++q) acc[nt][q] = 0.f;

        // hoist A chunks: h_hi 0-3, x/bias chunk 4
        uint32_t ah[4][4], ax[4];
        #pragma unroll
        for (int c = 0; c < 4; ++c) LDSM4(ah[c], aB + a_l + (uint32_t)(c * 32));
        LDSM4(ax, aB + a_l + (uint32_t)(4 * 32));

        // prefetch x(t+1) during GEMM
        float xr[IDIM];
        const bool dox = is_xw && (t + 1 < T_STEPS);
        if (dox) {
            #pragma unroll
            for (int i = 0; i < IDIM; ++i) xr[i] = __ldg(xp + (t + 1) * IDIM + i);
        }

        // ---- pipelined: MMA(p+1) issues before epilogue(p) ----
        MMA_PASS_REG(0);
        #pragma unroll
        for (int p = 0; p < 4; ++p) {
            if (p == 0) MMA_PASS_REG(1);
            else if (p == 1) MMA_PASS_LDS(2);
            else if (p == 2) MMA_PASS_LDS(3);

            // paired f16x2 epilogue for pass p's 2 cells (rh = 0,1):
            // (i,f) adjacent in even tile, (g,o) adjacent in odd tile.
            __half2 tif0 = tanh2(__floats2half2_rn(acc[2 * p][0], acc[2 * p][1]));
            __half2 tgo0 = tanh2(__floats2half2_rn(acc[2 * p + 1][0], acc[2 * p + 1][1]));
            __half2 tif1 = tanh2(__floats2half2_rn(acc[2 * p][2], acc[2 * p][3]));
            __half2 tgo1 = tanh2(__floats2half2_rn(acc[2 * p + 1][2], acc[2 * p + 1][3]));
            __half2 sif0 = __hfma2(tif0, H55, H55);     // (ig, fg)
            __half2 sif1 = __hfma2(tif1, H55, H55);
            __half2 sgo0 = __hfma2(tgo0, H105, H005);   // (gg, og)
            __half2 sgo1 = __hfma2(tgo1, H105, H005);
            __half2 pr0 = __hmul2(sif0, sgo0);          // low = ig*gg
            __half2 pr1 = __hmul2(sif1, sgo1);
            float cn0 = fmaf(__high2float(sif0), cst[2 * p],     __low2float(pr0));
            float cn1 = fmaf(__high2float(sif1), cst[2 * p + 1], __low2float(pr1));
            cst[2 * p]     = cn0;
            cst[2 * p + 1] = cn1;
            __half2 tc = tanh2(__floats2half2_rn(cn0, cn1));
            __half2 og2 = __halves2half2(__high2half(sgo0), __high2half(sgo1));
            __half2 h2 = __hmul2(og2, tc);              // (h_rh0, h_rh1) in f16

            int j = (ncol >> 2) + p * 4 + ejq;
            *(__half*)(anext + (mrow + erow0) * SA + j * 2)     = __low2half(h2);
            *(__half*)(anext + (mrow + erow0 + 8) * SA + j * 2) = __high2half(h2);
            if (t == T_STEPS - 1) {
                hf[(mrow + erow0) * 68 + j]     = __low2float(h2);
                hf[(mrow + erow0 + 8) * 68 + j] = __high2float(h2);
            }
        }

        // store x(t+1)
        if (dox) {
            char* ab = anext + xrow * SA;
            #pragma unroll
            for (int i = 0; i < IDIM; ++i) {
                __half hh = __float2half_rn(xr[i]);
                *(__half*)(ab + (64 + i) * 2) = hh;
                *(__half*)(ab + (71 + i) * 2) = hh;
            }
        }

        asm volatile("bar.sync %0, %1;" :: "r"(grp + 1), "r"(128) : "memory");
    }

    __syncthreads();

    // ---- final FC ----
    if (tid < 128) {
        int b  = tid >> 1;
        int ob = (tid & 1) * 8;
        float acc_o[8];
        #pragma unroll
        for (int oo = 0; oo < 8; ++oo) acc_o[oo] = bfc[ob + oo];
        for (int kk = 0; kk < HID; kk += 4) {
            float4 hv = *(float4*)&hf[b * 68 + kk];
            #pragma unroll
            for (int oo = 0; oo < 8; ++oo) {
                float4 wf = *(float4*)&wfc[(ob + oo) * HID + kk];
                acc_o[oo] += hv.x * wf.x + hv.y * wf.y + hv.z * wf.z + hv.w * wf.w;
            }
        }
        #pragma unroll
        for (int oo = 0; oo < 8; ++oo)
            out[(size_t)(bbase + b) * ODIM + ob + oo] = acc_o[oo];
    }
}

extern "C" void kernel_launch(void* const* d_in, const int* in_sizes, int n_in,
                              void* d_out, int out_size) {
    const float* x    = (const float*)d_in[0];
    const float* W_ih = (const float*)d_in[1];
    const float* W_hh = (const float*)d_in[2];
    const float* b_ih = (const float*)d_in[3];
    const float* b_hh = (const float*)d_in[4];
    const float* W_fc = (const float*)d_in[5];
    const float* b_fc = (const float*)d_in[6];
    float* out = (float*)d_out;

    int B = in_sizes[0] / (T_STEPS * IDIM);   // 8192
    int nblocks = B / TB;                     // 128

    cudaFuncSetAttribute(lstm_mma, cudaFuncAttributeMaxDynamicSharedMemorySize, SMEM_TOTAL);
    lstm_mma<<<nblocks, NTHR, SMEM_TOTAL>>>(x, W_ih, W_hh, b_ih, b_hh, W_fc, b_fc, out);
}